// round 3
// baseline (speedup 1.0000x reference)
#include <cuda_runtime.h>
#include <cstdint>

#define NTOK   4096
#define NV     204
#define NH     128
#define NH2    256
#define ROWS   32
#define VC     4
#define VPC    51
#define NTILES 128

__device__ float g_partial[VC][NTOK * NH];
__device__ float g_wtsT[NV * NTOK];

__device__ __forceinline__ unsigned long long pk2(float x, float y) {
    unsigned long long r;
    asm("mov.b64 %0, {%1, %2};" : "=l"(r) : "f"(x), "f"(y));
    return r;
}
__device__ __forceinline__ void ffma2(unsigned long long &d, unsigned long long a, unsigned long long b) {
    asm("fma.rn.f32x2 %0, %1, %2, %0;" : "+l"(d) : "l"(a), "l"(b));
}
__device__ __forceinline__ float upk_sum(unsigned long long v) {
    float lo, hi;
    asm("mov.b64 {%0, %1}, %2;" : "=f"(lo), "=f"(hi) : "l"(v));
    return lo + hi;
}
__device__ __forceinline__ float warp_sum(float s) {
    #pragma unroll
    for (int o = 16; o > 0; o >>= 1) s += __shfl_xor_sync(0xffffffffu, s, o);
    return s;
}
__device__ __forceinline__ float warp_max(float s) {
    #pragma unroll
    for (int o = 16; o > 0; o >>= 1) s = fmaxf(s, __shfl_xor_sync(0xffffffffu, s, o));
    return s;
}
__device__ __forceinline__ float elu1(float t) { return t > 0.f ? t : expm1f(t); }

// ============== Kernel 1: weights branch -> wts ==============
__global__ __launch_bounds__(256) void wts_kernel(
    const float* __restrict__ x,
    const float* __restrict__ wfc1_w, const float* __restrict__ wfc1_b,
    const float* __restrict__ wfc2_w, const float* __restrict__ wfc2_b,
    const float* __restrict__ wglu_w, const float* __restrict__ wglu_b,
    const float* __restrict__ wln_g,  const float* __restrict__ wln_b,
    float* __restrict__ wts_out)
{
    __shared__ float sx[8][NV];
    __shared__ float sa[8][NH];
    __shared__ float sb[8][NH];
    __shared__ float sg[8][2 * NV];

    const int tid = threadIdx.x;
    const int n0  = blockIdx.x * 8;

    for (int i = tid; i < 8 * NV; i += 256) sx[i / NV][i % NV] = x[n0 * NV + i];
    __syncthreads();

    const int h  = tid & 127;
    const int rh = tid >> 7;

    { // a1 = elu(xs @ wfc1_w + b)
        float acc[4];
        float bia = wfc1_b[h];
        #pragma unroll
        for (int i = 0; i < 4; i++) acc[i] = bia;
        for (int v = 0; v < NV; v++) {
            float w = wfc1_w[v * NH + h];
            #pragma unroll
            for (int i = 0; i < 4; i++) acc[i] += sx[rh * 4 + i][v] * w;
        }
        #pragma unroll
        for (int i = 0; i < 4; i++) sa[rh * 4 + i][h] = elu1(acc[i]);
    }
    __syncthreads();

    { // a2 = a1 @ wfc2_w + b
        float acc[4];
        float bia = wfc2_b[h];
        #pragma unroll
        for (int i = 0; i < 4; i++) acc[i] = bia;
        for (int k = 0; k < NH; k++) {
            float w = wfc2_w[k * NH + h];
            #pragma unroll
            for (int i = 0; i < 4; i++) acc[i] += sa[rh * 4 + i][k] * w;
        }
        #pragma unroll
        for (int i = 0; i < 4; i++) sb[rh * 4 + i][h] = acc[i];
    }
    __syncthreads();

    // g = a2 @ wglu_w + b (2V = 408 cols)
    for (int jb = 0; jb < 2 * NV; jb += 256) {
        int j = jb + tid;
        if (j < 2 * NV) {
            float acc[8];
            float bia = wglu_b[j];
            #pragma unroll
            for (int r = 0; r < 8; r++) acc[r] = bia;
            for (int k = 0; k < NH; k++) {
                float w = wglu_w[k * 2 * NV + j];
                #pragma unroll
                for (int r = 0; r < 8; r++) acc[r] += sb[r][k] * w;
            }
            #pragma unroll
            for (int r = 0; r < 8; r++) sg[r][j] = acc[r];
        }
    }
    __syncthreads();

    // per-row GLU + LN over V + softmax
    const int r = tid >> 5, l = tid & 31;
    float y[7];
    #pragma unroll
    for (int p = 0; p < 7; p++) {
        int v = l + 32 * p;
        if (v < NV) {
            float fo  = sg[r][v];
            float gt  = sg[r][v + NV];
            float sig = 1.f / (1.f + expf(-gt));
            y[p] = sx[r][v] + fo * sig;
        } else y[p] = 0.f;
    }
    float s = 0.f;
    #pragma unroll
    for (int p = 0; p < 7; p++) s += y[p];
    float mean = warp_sum(s) * (1.f / (float)NV);

    float s2 = 0.f;
    #pragma unroll
    for (int p = 0; p < 7; p++) {
        int v = l + 32 * p;
        if (v < NV) { float d = y[p] - mean; s2 += d * d; }
    }
    float rs = rsqrtf(warp_sum(s2) * (1.f / (float)NV) + 1e-5f);

    float z[7]; float zmax = -1e30f;
    #pragma unroll
    for (int p = 0; p < 7; p++) {
        int v = l + 32 * p;
        if (v < NV) {
            z[p] = (y[p] - mean) * rs * wln_g[v] + wln_b[v];
            zmax = fmaxf(zmax, z[p]);
        } else z[p] = -1e30f;
    }
    zmax = warp_max(zmax);
    float es = 0.f;
    #pragma unroll
    for (int p = 0; p < 7; p++) {
        int v = l + 32 * p;
        if (v < NV) { z[p] = expf(z[p] - zmax); es += z[p]; }
    }
    float inv = 1.f / warp_sum(es);
    #pragma unroll
    for (int p = 0; p < 7; p++) {
        int v = l + 32 * p;
        if (v < NV) {
            float wt = z[p] * inv;
            wts_out[(n0 + r) * NV + v] = wt;
            g_wtsT[v * NTOK + n0 + r]  = wt;
        }
    }
}

// ============== Kernel 2: per-variable GRN + weighted accumulate ==============
// smem offsets (floats)
#define SM_A    0
#define SM_C    4096
#define SM_G    8192
#define SM_P    12288
#define SM_X    16896
#define SM_F1W  23424
#define SM_F1B  23552
#define SM_F2B  23680
#define SM_SKW  23808
#define SM_SKB  23936
#define SM_LNG  24064
#define SM_LNB  24192
#define SM_GLB  24320
#define SM_WTS  24576
#define SM_TOT  24608
#define SMEM_BYTES (SM_TOT * 4)

__global__ void __launch_bounds__(256, 2) main_kernel(
    const float* __restrict__ x,
    const float* __restrict__ fc1_w, const float* __restrict__ fc1_b,
    const float* __restrict__ fc2_w, const float* __restrict__ fc2_b,
    const float* __restrict__ glu_w, const float* __restrict__ glu_b,
    const float* __restrict__ skip_w, const float* __restrict__ skip_b,
    const float* __restrict__ ln_g,  const float* __restrict__ ln_b)
{
    extern __shared__ float sm[];
    const int tid  = threadIdx.x;
    const int wid  = tid >> 5;
    const int lane = tid & 31;
    const int n0   = blockIdx.x * ROWS;
    const int vc   = blockIdx.y;

    for (int i = tid; i < ROWS * NV; i += 256) sm[SM_X + i] = x[n0 * NV + i];
    if (tid < NH) { sm[SM_LNG + tid] = ln_g[tid]; sm[SM_LNB + tid] = ln_b[tid]; }
    __syncthreads();

    float facc[4][4];
    #pragma unroll
    for (int i = 0; i < 4; i++)
        #pragma unroll
        for (int j = 0; j < 4; j++) facc[i][j] = 0.f;

    for (int vi = 0; vi < VPC; vi++) {
        const int v = vc * VPC + vi;

        if (tid < NH) {
            sm[SM_F1W + tid] = fc1_w[v * NH + tid];
            sm[SM_F1B + tid] = fc1_b[v * NH + tid];
            sm[SM_F2B + tid] = fc2_b[v * NH + tid];
            sm[SM_SKW + tid] = skip_w[v * NH + tid];
            sm[SM_SKB + tid] = skip_b[v * NH + tid];
        }
        sm[SM_GLB + tid] = glu_b[v * NH2 + tid];
        if (tid < ROWS) sm[SM_WTS + tid] = g_wtsT[v * NTOK + n0 + tid];
        __syncthreads();

        // stage 1: H1 = elu(x*fc1_w + fc1_b)
        for (int i = tid; i < ROWS * NH; i += 256) {
            int r = i >> 7, hh = i & 127;
            sm[SM_A + i] = elu1(sm[SM_X + r * NV + v] * sm[SM_F1W + hh] + sm[SM_F1B + hh]);
        }
        __syncthreads();

        // GEMM1: H2 = H1 @ fc2_w[v] + fc2_b[v] (scalar FFMA)
        {
            float acc[4][4];
            #pragma unroll
            for (int i = 0; i < 4; i++)
                #pragma unroll
                for (int j = 0; j < 4; j++) acc[i][j] = 0.f;

            const float* Wv = fc2_w + (size_t)v * NH * NH;
            for (int kp = 0; kp < 4; kp++) {
                #pragma unroll
                for (int q = 0; q < 4; q++) {
                    int lin = tid + q * 256;
                    int kk = lin >> 5, c4 = lin & 31;
                    float4 w4 = *(const float4*)(Wv + (kp * 32 + kk) * NH + c4 * 4);
                    *(float4*)(sm + SM_P + kk * 132 + c4 * 4) = w4;
                }
                __syncthreads();
                #pragma unroll 8
                for (int k = 0; k < 32; k++) {
                    float4 b = *(const float4*)(sm + SM_P + k * 132 + lane * 4);
                    #pragma unroll
                    for (int i = 0; i < 4; i++) {
                        float a = sm[SM_A + (wid * 4 + i) * NH + kp * 32 + k];
                        acc[i][0] += a * b.x; acc[i][1] += a * b.y;
                        acc[i][2] += a * b.z; acc[i][3] += a * b.w;
                    }
                }
                __syncthreads();
            }
            #pragma unroll
            for (int i = 0; i < 4; i++) {
                float4 o;
                o.x = acc[i][0] + sm[SM_F2B + lane * 4 + 0];
                o.y = acc[i][1] + sm[SM_F2B + lane * 4 + 1];
                o.z = acc[i][2] + sm[SM_F2B + lane * 4 + 2];
                o.w = acc[i][3] + sm[SM_F2B + lane * 4 + 3];
                *(float4*)(sm + SM_C + (wid * 4 + i) * NH + lane * 4) = o;
            }
            __syncthreads();
        }

        // GEMM2: fc_out / gate = H2 @ glu_w[v][g][:]^T  (f32x2)
        for (int half = 0; half < 2; half++) {
            unsigned long long acc2[4][4];
            #pragma unroll
            for (int i = 0; i < 4; i++)
                #pragma unroll
                for (int j = 0; j < 4; j++) acc2[i][j] = 0ull;

            const float* W2 = glu_w + (size_t)v * NH2 * NH + (size_t)half * NH * NH;
            for (int hp = 0; hp < 4; hp++) {
                #pragma unroll
                for (int q = 0; q < 4; q++) {
                    int lin = tid + q * 256;
                    int g = lin >> 3, h4 = lin & 7;
                    float4 w4 = *(const float4*)(W2 + g * NH + hp * 32 + h4 * 4);
                    *(float4*)(sm + SM_P + (g * 9 + h4) * 4) = w4;
                }
                __syncthreads();
                #pragma unroll
                for (int k4 = 0; k4 < 8; k4++) {
                    unsigned long long b01[4], b23[4];
                    #pragma unroll
                    for (int j = 0; j < 4; j++) {
                        float4 b = *(const float4*)(sm + SM_P + ((lane + 32 * j) * 9 + k4) * 4);
                        b01[j] = pk2(b.x, b.y);
                        b23[j] = pk2(b.z, b.w);
                    }
                    #pragma unroll
                    for (int i = 0; i < 4; i++) {
                        float4 a = *(const float4*)(sm + SM_C + (wid * 4 + i) * NH + hp * 32 + k4 * 4);
                        unsigned long long a01 = pk2(a.x, a.y), a23 = pk2(a.z, a.w);
                        #pragma unroll
                        for (int j = 0; j < 4; j++) {
                            ffma2(acc2[i][j], a01, b01[j]);
                            ffma2(acc2[i][j], a23, b23[j]);
                        }
                    }
                }
                __syncthreads();
            }
            float* dstp = sm + (half ? SM_G : SM_A);
            #pragma unroll
            for (int i = 0; i < 4; i++)
                #pragma unroll
                for (int j = 0; j < 4; j++) {
                    int c = lane + 32 * j;
                    dstp[(wid * 4 + i) * NH + c] = upk_sum(acc2[i][j]) + sm[SM_GLB + half * NH + c];
                }
        }
        __syncthreads();

        // stage 4: GLU + skip + LayerNorm + weighted accumulate
        #pragma unroll
        for (int it = 0; it < 4; it++) {
            int r = wid * 4 + it;
            float4 f  = *(const float4*)(sm + SM_A + r * NH + lane * 4);
            float4 gt = *(const float4*)(sm + SM_G + r * NH + lane * 4);
            float xv  = sm[SM_X + r * NV + v];
            float val[4];
            const float* fp = &f.x;
            const float* gp = &gt.x;
            #pragma unroll
            for (int j = 0; j < 4; j++) {
                float sig = 1.f / (1.f + __expf(-gp[j]));
                val[j] = fp[j] * sig + xv * sm[SM_SKW + lane * 4 + j] + sm[SM_SKB + lane * 4 + j];
            }
            float s = val[0] + val[1] + val[2] + val[3];
            float mean = warp_sum(s) * (1.f / 128.f);
            float d2 = 0.f;
            #pragma unroll
            for (int j = 0; j < 4; j++) { float d = val[j] - mean; d2 += d * d; }
            float rs = rsqrtf(warp_sum(d2) * (1.f / 128.f) + 1e-5f);
            float wt = sm[SM_WTS + r];
            #pragma unroll
            for (int j = 0; j < 4; j++) {
                float nm = (val[j] - mean) * rs * sm[SM_LNG + lane * 4 + j] + sm[SM_LNB + lane * 4 + j];
                facc[it][j] += wt * nm;
            }
        }
        __syncthreads();
    }

    #pragma unroll
    for (int it = 0; it < 4; it++) {
        float4 o; o.x = facc[it][0]; o.y = facc[it][1]; o.z = facc[it][2]; o.w = facc[it][3];
        *(float4*)(&g_partial[vc][(n0 + wid * 4 + it) * NH + lane * 4]) = o;
    }
}

// ============== Kernel 3: reduce chunk partials ==============
__global__ __launch_bounds__(256) void reduce_kernel(float* __restrict__ out)
{
    int i = blockIdx.x * 256 + threadIdx.x;
    out[i] = g_partial[0][i] + g_partial[1][i] + g_partial[2][i] + g_partial[3][i];
}

extern "C" void kernel_launch(void* const* d_in, const int* in_sizes, int n_in,
                              void* d_out, int out_size) {
    const float* x      = (const float*)d_in[0];
    const float* fc1_w  = (const float*)d_in[1];
    const float* fc1_b  = (const float*)d_in[2];
    const float* fc2_w  = (const float*)d_in[3];
    const float* fc2_b  = (const float*)d_in[4];
    const float* glu_w  = (const float*)d_in[5];
    const float* glu_b  = (const float*)d_in[6];
    const float* skip_w = (const float*)d_in[7];
    const float* skip_b = (const float*)d_in[8];
    const float* ln_g   = (const float*)d_in[9];
    const float* ln_b   = (const float*)d_in[10];
    const float* wfc1_w = (const float*)d_in[11];
    const float* wfc1_b = (const float*)d_in[12];
    const float* wfc2_w = (const float*)d_in[13];
    const float* wfc2_b = (const float*)d_in[14];
    const float* wglu_w = (const float*)d_in[15];
    const float* wglu_b = (const float*)d_in[16];
    const float* wln_g  = (const float*)d_in[17];
    const float* wln_b  = (const float*)d_in[18];

    float* out = (float*)d_out;
    float* wts = out + (size_t)NTOK * NH;

    cudaFuncSetAttribute(main_kernel, cudaFuncAttributeMaxDynamicSharedMemorySize, SMEM_BYTES);

    wts_kernel<<<NTOK / 8, 256>>>(x, wfc1_w, wfc1_b, wfc2_w, wfc2_b,
                                  wglu_w, wglu_b, wln_g, wln_b, wts);
    main_kernel<<<dim3(NTILES, VC), 256, SMEM_BYTES>>>(
        x, fc1_w, fc1_b, fc2_w, fc2_b, glu_w, glu_b,
        skip_w, skip_b, ln_g, ln_b);
    reduce_kernel<<<(NTOK * NH) / 256, 256>>>(out);
}

// round 5
// speedup vs baseline: 1.3134x; 1.3134x over previous
#include <cuda_runtime.h>
#include <cstdint>

#define NTOK   4096
#define NV     204
#define NH     128
#define NH2    256
#define MROWS  64          // token rows per unit
#define NUNIT  8           // units per CTA (mg dimension covers 8*64=512 rows)

// ------------------------------------------------------------------
// Device scratch (no allocations allowed)
// ------------------------------------------------------------------
__device__ float g_wc[(size_t)NV * 64 * 256 * 2];   // combined weight, pair-interleaved:
                                                    // [v][k2][g] -> (Wc[2k2,g], Wc[2k2+1,g])
__device__ float g_bc[NV * 256];                    // combined bias per v
__device__ float g_vpart[(size_t)NV * NTOK * NH];   // per-variable weighted partials
__device__ float g_wtsT[NV * NTOK];

typedef unsigned long long ull;

__device__ __forceinline__ void ffma2(ull &d, ull a, ull b) {
    asm("fma.rn.f32x2 %0, %1, %2, %0;" : "+l"(d) : "l"(a), "l"(b));
}
__device__ __forceinline__ float upk_sum(ull v) {
    float lo, hi;
    asm("mov.b64 {%0, %1}, %2;" : "=f"(lo), "=f"(hi) : "l"(v));
    return lo + hi;
}
__device__ __forceinline__ float warp_sum(float s) {
    #pragma unroll
    for (int o = 16; o > 0; o >>= 1) s += __shfl_xor_sync(0xffffffffu, s, o);
    return s;
}
__device__ __forceinline__ float warp_max(float s) {
    #pragma unroll
    for (int o = 16; o > 0; o >>= 1) s = fmaxf(s, __shfl_xor_sync(0xffffffffu, s, o));
    return s;
}
__device__ __forceinline__ float elu1(float t) { return t > 0.f ? t : expm1f(t); }

// ------------------------------------------------------------------
// Prepass: Wc[v] = fc2_w[v] @ glu_w[v]^T  (contract over middle dim k)
//          bc[v] = fc2_b[v] @ glu_w[v]^T + glu_b[v]
// CTA per v, 256 threads.  f32x2 inner loops.
// smem: sA[h][k] stride 130 floats (pad 2), sB[g][k] stride 130, sf2b[128]
// ------------------------------------------------------------------
#define PREP_SA    0                      // 128*130 floats = 66560 B
#define PREP_SB    66560                  // 32*130 floats  = 16640 B
#define PREP_F2B   83200                  // 512 B
#define PREP_SMEM  83712

__global__ __launch_bounds__(256) void prep_wc(
    const float* __restrict__ fc2_w, const float* __restrict__ fc2_b,
    const float* __restrict__ glu_w, const float* __restrict__ glu_b)
{
    extern __shared__ char smraw[];
    float* sA   = (float*)(smraw + PREP_SA);
    float* sB   = (float*)(smraw + PREP_SB);
    float* sf2b = (float*)(smraw + PREP_F2B);

    const int tid = threadIdx.x;
    const int v   = blockIdx.x;

    for (int i = tid; i < 16384; i += 256) {
        int h = i >> 7, k = i & 127;
        sA[h * 130 + k] = fc2_w[(size_t)v * 16384 + i];
    }
    if (tid < 128) sf2b[tid] = fc2_b[v * NH + tid];
    __syncthreads();

    const int h  = tid & 127;
    const int g0 = (tid >> 7) * 16;

    for (int gt = 0; gt < 8; gt++) {
        for (int i = tid; i < 4096; i += 256) {
            int g = i >> 7, k = i & 127;
            sB[g * 130 + k] = glu_w[(size_t)v * 32768 + gt * 4096 + i];
        }
        __syncthreads();

        ull acc[16];
        #pragma unroll
        for (int j = 0; j < 16; j++) acc[j] = 0ull;

        #pragma unroll 4
        for (int k2 = 0; k2 < 64; k2++) {
            ull a = *(const ull*)(sA + h * 130 + 2 * k2);
            #pragma unroll
            for (int j = 0; j < 16; j++)
                ffma2(acc[j], a, *(const ull*)(sB + (g0 + j) * 130 + 2 * k2));
        }
        #pragma unroll
        for (int j = 0; j < 16; j++) {
            int g = gt * 32 + g0 + j;
            g_wc[((size_t)(v * 64 + (h >> 1)) * 256 + g) * 2 + (h & 1)] = upk_sum(acc[j]);
        }
        // bc for this g-tile (first 32 threads)
        if (tid < 32) {
            float s = 0.f;
            for (int k = 0; k < 128; k++) s += sf2b[k] * sB[tid * 130 + k];
            g_bc[v * 256 + gt * 32 + tid] = s + glu_b[(size_t)v * 256 + gt * 32 + tid];
        }
        __syncthreads();
    }
}

// ------------------------------------------------------------------
// Kernel 1: weights branch -> softmax wts (unchanged, known-correct)
// ------------------------------------------------------------------
__global__ __launch_bounds__(256) void wts_kernel(
    const float* __restrict__ x,
    const float* __restrict__ wfc1_w, const float* __restrict__ wfc1_b,
    const float* __restrict__ wfc2_w, const float* __restrict__ wfc2_b,
    const float* __restrict__ wglu_w, const float* __restrict__ wglu_b,
    const float* __restrict__ wln_g,  const float* __restrict__ wln_b,
    float* __restrict__ wts_out)
{
    __shared__ float sx[8][NV];
    __shared__ float sa[8][NH];
    __shared__ float sb[8][NH];
    __shared__ float sg[8][2 * NV];

    const int tid = threadIdx.x;
    const int n0  = blockIdx.x * 8;

    for (int i = tid; i < 8 * NV; i += 256) sx[i / NV][i % NV] = x[n0 * NV + i];
    __syncthreads();

    const int h  = tid & 127;
    const int rh = tid >> 7;

    {
        float acc[4];
        float bia = wfc1_b[h];
        #pragma unroll
        for (int i = 0; i < 4; i++) acc[i] = bia;
        for (int v = 0; v < NV; v++) {
            float w = wfc1_w[v * NH + h];
            #pragma unroll
            for (int i = 0; i < 4; i++) acc[i] += sx[rh * 4 + i][v] * w;
        }
        #pragma unroll
        for (int i = 0; i < 4; i++) sa[rh * 4 + i][h] = elu1(acc[i]);
    }
    __syncthreads();

    {
        float acc[4];
        float bia = wfc2_b[h];
        #pragma unroll
        for (int i = 0; i < 4; i++) acc[i] = bia;
        for (int k = 0; k < NH; k++) {
            float w = wfc2_w[k * NH + h];
            #pragma unroll
            for (int i = 0; i < 4; i++) acc[i] += sa[rh * 4 + i][k] * w;
        }
        #pragma unroll
        for (int i = 0; i < 4; i++) sb[rh * 4 + i][h] = acc[i];
    }
    __syncthreads();

    for (int jb = 0; jb < 2 * NV; jb += 256) {
        int j = jb + tid;
        if (j < 2 * NV) {
            float acc[8];
            float bia = wglu_b[j];
            #pragma unroll
            for (int r = 0; r < 8; r++) acc[r] = bia;
            for (int k = 0; k < NH; k++) {
                float w = wglu_w[k * 2 * NV + j];
                #pragma unroll
                for (int r = 0; r < 8; r++) acc[r] += sb[r][k] * w;
            }
            #pragma unroll
            for (int r = 0; r < 8; r++) sg[r][j] = acc[r];
        }
    }
    __syncthreads();

    const int r = tid >> 5, l = tid & 31;
    float y[7];
    #pragma unroll
    for (int p = 0; p < 7; p++) {
        int v = l + 32 * p;
        if (v < NV) {
            float fo  = sg[r][v];
            float gt  = sg[r][v + NV];
            float sig = 1.f / (1.f + expf(-gt));
            y[p] = sx[r][v] + fo * sig;
        } else y[p] = 0.f;
    }
    float s = 0.f;
    #pragma unroll
    for (int p = 0; p < 7; p++) s += y[p];
    float mean = warp_sum(s) * (1.f / (float)NV);

    float s2 = 0.f;
    #pragma unroll
    for (int p = 0; p < 7; p++) {
        int v = l + 32 * p;
        if (v < NV) { float d = y[p] - mean; s2 += d * d; }
    }
    float rs = rsqrtf(warp_sum(s2) * (1.f / (float)NV) + 1e-5f);

    float z[7]; float zmax = -1e30f;
    #pragma unroll
    for (int p = 0; p < 7; p++) {
        int v = l + 32 * p;
        if (v < NV) {
            z[p] = (y[p] - mean) * rs * wln_g[v] + wln_b[v];
            zmax = fmaxf(zmax, z[p]);
        } else z[p] = -1e30f;
    }
    zmax = warp_max(zmax);
    float es = 0.f;
    #pragma unroll
    for (int p = 0; p < 7; p++) {
        int v = l + 32 * p;
        if (v < NV) { z[p] = expf(z[p] - zmax); es += z[p]; }
    }
    float inv = 1.f / warp_sum(es);
    #pragma unroll
    for (int p = 0; p < 7; p++) {
        int v = l + 32 * p;
        if (v < NV) {
            float wt = z[p] * inv;
            wts_out[(n0 + r) * NV + v] = wt;
            g_wtsT[v * NTOK + n0 + r]  = wt;
        }
    }
}

// ------------------------------------------------------------------
// Main kernel: CTA = (mg in 0..7, v).  Wc[v] fully smem-resident.
// Per unit (64 rows): stage1 elu -> A pairs; GEMM 64x256 via f32x2;
// epilogue GLU+skip+rowLN+weight -> g_vpart[v].
// smem layout (bytes):
// ------------------------------------------------------------------
#define MB_BP   0                         // 64 k2 * 256 g * 8B = 131072
#define MB_AH   131072                    // 64 r * 64 k2 * 8B  = 32768
#define MB_SX   163840                    // 64 floats
#define MB_SWT  164096                    // 64 floats
#define MB_F1W  164352                    // 128 floats
#define MB_F1B  164864
#define MB_SKW  165376
#define MB_SKB  165888
#define MB_LNG  166400
#define MB_LNB  166912
#define MB_BC   167424                    // 256 floats
#define MB_SMEM 168448

__global__ __launch_bounds__(256, 1) void tc2_main(
    const float* __restrict__ x,
    const float* __restrict__ fc1_w, const float* __restrict__ fc1_b,
    const float* __restrict__ skip_w, const float* __restrict__ skip_b,
    const float* __restrict__ ln_g,  const float* __restrict__ ln_b)
{
    extern __shared__ char smraw[];
    float* bp   = (float*)(smraw + MB_BP);    // [k2*256 + g] as float2 pairs
    float* aH   = (float*)(smraw + MB_AH);    // [r*64 + k2] as float2 pairs
    float* sx   = (float*)(smraw + MB_SX);
    float* swt  = (float*)(smraw + MB_SWT);
    float* sf1w = (float*)(smraw + MB_F1W);
    float* sf1b = (float*)(smraw + MB_F1B);
    float* sskw = (float*)(smraw + MB_SKW);
    float* sskb = (float*)(smraw + MB_SKB);
    float* slng = (float*)(smraw + MB_LNG);
    float* slnb = (float*)(smraw + MB_LNB);
    float* sbc  = (float*)(smraw + MB_BC);

    const int tid = threadIdx.x;
    const int v   = blockIdx.y;
    const int mg  = blockIdx.x;

    // load Wc[v] (128 KB) once
    {
        const float4* src = (const float4*)(g_wc + (size_t)v * 32768);
        float4* dst = (float4*)bp;
        for (int i = tid; i < 8192; i += 256) dst[i] = src[i];
    }
    if (tid < 128) {
        sf1w[tid] = fc1_w[v * NH + tid];
        sf1b[tid] = fc1_b[v * NH + tid];
        sskw[tid] = skip_w[v * NH + tid];
        sskb[tid] = skip_b[v * NH + tid];
        slng[tid] = ln_g[tid];
        slnb[tid] = ln_b[tid];
    }
    sbc[tid] = g_bc[v * 256 + tid];
    __syncthreads();

    const int w  = tid >> 5;
    const int l  = tid & 31;
    const int r0 = w * 8;

    for (int mi = 0; mi < NUNIT; mi++) {
        const int n0 = (mg * NUNIT + mi) * MROWS;

        if (tid < 64) {
            sx[tid]  = x[(size_t)(n0 + tid) * NV + v];
            swt[tid] = g_wtsT[v * NTOK + n0 + tid];
        }
        __syncthreads();

        // stage1: A pairs = elu(x*f1w + f1b)
        {
            int r  = tid >> 2;
            int kb = (tid & 3) * 16;
            float xv = sx[r];
            #pragma unroll
            for (int j = 0; j < 16; j++) {
                int k2 = kb + j;
                float t0 = elu1(xv * sf1w[2 * k2]     + sf1b[2 * k2]);
                float t1 = elu1(xv * sf1w[2 * k2 + 1] + sf1b[2 * k2 + 1]);
                *(float2*)(aH + (r * 64 + k2) * 2) = make_float2(t0, t1);
            }
        }
        __syncthreads();

        // GEMM: acc[r][c] ; c 0..3 = fc cols 4l..4l+3 ; c 4..7 = gate cols 128+4l..
        ull acc[8][8];
        #pragma unroll
        for (int i = 0; i < 8; i++)
            #pragma unroll
            for (int j = 0; j < 8; j++) acc[i][j] = 0ull;

        #pragma unroll 2
        for (int k2 = 0; k2 < 64; k2++) {
            ull a[8];
            #pragma unroll
            for (int r = 0; r < 8; r++)
                a[r] = *(const ull*)(aH + ((r0 + r) * 64 + k2) * 2);
            const ull* brow = (const ull*)(bp + k2 * 512);
            ulonglong2 bf0 = *(const ulonglong2*)(brow + 4 * l);
            ulonglong2 bf1 = *(const ulonglong2*)(brow + 4 * l + 2);
            ulonglong2 bg0 = *(const ulonglong2*)(brow + 128 + 4 * l);
            ulonglong2 bg1 = *(const ulonglong2*)(brow + 128 + 4 * l + 2);
            ull b[8] = {bf0.x, bf0.y, bf1.x, bf1.y, bg0.x, bg0.y, bg1.x, bg1.y};
            #pragma unroll
            for (int r = 0; r < 8; r++)
                #pragma unroll
                for (int c = 0; c < 8; c++)
                    ffma2(acc[r][c], a[r], b[c]);
        }

        // epilogue: per row GLU + skip + LN + weighted partial
        #pragma unroll
        for (int r = 0; r < 8; r++) {
            int row = r0 + r;
            float xv = sx[row];
            float val[4];
            #pragma unroll
            for (int j = 0; j < 4; j++) {
                int c = 4 * l + j;
                float fv = upk_sum(acc[r][j])     + sbc[c];
                float gv = upk_sum(acc[r][4 + j]) + sbc[128 + c];
                float sig = 1.f / (1.f + __expf(-gv));
                val[j] = fv * sig + xv * sskw[c] + sskb[c];
            }
            float s = val[0] + val[1] + val[2] + val[3];
            float mean = warp_sum(s) * (1.f / 128.f);
            float d2 = 0.f;
            #pragma unroll
            for (int j = 0; j < 4; j++) { float d = val[j] - mean; d2 += d * d; }
            float rs = rsqrtf(warp_sum(d2) * (1.f / 128.f) + 1e-5f);
            float wt = swt[row];
            float4 o;
            o.x = wt * ((val[0] - mean) * rs * slng[4 * l + 0] + slnb[4 * l + 0]);
            o.y = wt * ((val[1] - mean) * rs * slng[4 * l + 1] + slnb[4 * l + 1]);
            o.z = wt * ((val[2] - mean) * rs * slng[4 * l + 2] + slnb[4 * l + 2]);
            o.w = wt * ((val[3] - mean) * rs * slng[4 * l + 3] + slnb[4 * l + 3]);
            *(float4*)(g_vpart + (size_t)v * ((size_t)NTOK * NH)
                       + (size_t)(n0 + row) * NH + 4 * l) = o;
        }
        __syncthreads();
    }
}

// ------------------------------------------------------------------
// Reduce: sum 204 per-variable partials -> out
// ------------------------------------------------------------------
__global__ __launch_bounds__(256) void reduce_kernel(float* __restrict__ out)
{
    int i = blockIdx.x * 256 + threadIdx.x;
    const float* p = g_vpart + i;
    float s = 0.f;
    #pragma unroll 4
    for (int v = 0; v < NV; v++) s += p[(size_t)v * ((size_t)NTOK * NH)];
    out[i] = s;
}

// ------------------------------------------------------------------
extern "C" void kernel_launch(void* const* d_in, const int* in_sizes, int n_in,
                              void* d_out, int out_size) {
    const float* x      = (const float*)d_in[0];
    const float* fc1_w  = (const float*)d_in[1];
    const float* fc1_b  = (const float*)d_in[2];
    const float* fc2_w  = (const float*)d_in[3];
    const float* fc2_b  = (const float*)d_in[4];
    const float* glu_w  = (const float*)d_in[5];
    const float* glu_b  = (const float*)d_in[6];
    const float* skip_w = (const float*)d_in[7];
    const float* skip_b = (const float*)d_in[8];
    const float* ln_g   = (const float*)d_in[9];
    const float* ln_b   = (const float*)d_in[10];
    const float* wfc1_w = (const float*)d_in[11];
    const float* wfc1_b = (const float*)d_in[12];
    const float* wfc2_w = (const float*)d_in[13];
    const float* wfc2_b = (const float*)d_in[14];
    const float* wglu_w = (const float*)d_in[15];
    const float* wglu_b = (const float*)d_in[16];
    const float* wln_g  = (const float*)d_in[17];
    const float* wln_b  = (const float*)d_in[18];

    float* out = (float*)d_out;
    float* wts = out + (size_t)NTOK * NH;

    cudaFuncSetAttribute(prep_wc,  cudaFuncAttributeMaxDynamicSharedMemorySize, PREP_SMEM);
    cudaFuncSetAttribute(tc2_main, cudaFuncAttributeMaxDynamicSharedMemorySize, MB_SMEM);

    prep_wc<<<NV, 256, PREP_SMEM>>>(fc2_w, fc2_b, glu_w, glu_b);
    wts_kernel<<<NTOK / 8, 256>>>(x, wfc1_w, wfc1_b, wfc2_w, wfc2_b,
                                  wglu_w, wglu_b, wln_g, wln_b, wts);
    tc2_main<<<dim3(NUNIT, NV), 256, MB_SMEM>>>(
        x, fc1_w, fc1_b, skip_w, skip_b, ln_g, ln_b);
    reduce_kernel<<<(NTOK * NH) / 256, 256>>>(out);
}

// round 8
// speedup vs baseline: 1.6380x; 1.2471x over previous
#include <cuda_runtime.h>
#include <cuda_bf16.h>
#include <cstdint>

#define NTOK   4096
#define NV     204
#define NH     128
#define NH2    256

// ------------------------------------------------------------------
// Device scratch (zero-init, no allocations)
// ------------------------------------------------------------------
// Combined weight Wc[v][k=128][n=256] as bf16 hi/lo, pair-packed over k:
// word(k2, n) = bf16(Wc[2k2][n]) | bf16(Wc[2k2+1][n])<<16, row stride 264 words.
__device__ __nv_bfloat16 g_bhi[(size_t)NV * 64 * 528];
__device__ __nv_bfloat16 g_blo[(size_t)NV * 64 * 528];
__device__ float g_bc[NV * 256];
__device__ float g_vpart[(size_t)NV * NTOK * NH];
__device__ float g_wtsT[NV * NTOK];

typedef unsigned long long ull;
typedef uint32_t u32;

__device__ __forceinline__ void ffma2(ull &d, ull a, ull b) {
    asm("fma.rn.f32x2 %0, %1, %2, %0;" : "+l"(d) : "l"(a), "l"(b));
}
__device__ __forceinline__ float upk_sum(ull v) {
    float lo, hi;
    asm("mov.b64 {%0, %1}, %2;" : "=f"(lo), "=f"(hi) : "l"(v));
    return lo + hi;
}
__device__ __forceinline__ float warp_sum(float s) {
    #pragma unroll
    for (int o = 16; o > 0; o >>= 1) s += __shfl_xor_sync(0xffffffffu, s, o);
    return s;
}
__device__ __forceinline__ float warp_max(float s) {
    #pragma unroll
    for (int o = 16; o > 0; o >>= 1) s = fmaxf(s, __shfl_xor_sync(0xffffffffu, s, o));
    return s;
}
__device__ __forceinline__ float elu1(float t) { return t > 0.f ? t : expm1f(t); }

__device__ __forceinline__ void mma16816(float* d, u32 a0, u32 a1, u32 a2, u32 a3,
                                         u32 b0, u32 b1) {
    asm volatile("mma.sync.aligned.m16n8k16.row.col.f32.bf16.bf16.f32 "
        "{%0,%1,%2,%3}, {%4,%5,%6,%7}, {%8,%9}, {%0,%1,%2,%3};"
        : "+f"(d[0]), "+f"(d[1]), "+f"(d[2]), "+f"(d[3])
        : "r"(a0), "r"(a1), "r"(a2), "r"(a3), "r"(b0), "r"(b1));
}
__device__ __forceinline__ void split2(float t0, float t1, u32 &wh, u32 &wl) {
    __nv_bfloat16 h0 = __float2bfloat16(t0);
    __nv_bfloat16 l0 = __float2bfloat16(t0 - __bfloat162float(h0));
    __nv_bfloat16 h1 = __float2bfloat16(t1);
    __nv_bfloat16 l1 = __float2bfloat16(t1 - __bfloat162float(h1));
    wh = (u32)__bfloat16_as_ushort(h0) | ((u32)__bfloat16_as_ushort(h1) << 16);
    wl = (u32)__bfloat16_as_ushort(l0) | ((u32)__bfloat16_as_ushort(l1) << 16);
}

// ------------------------------------------------------------------
// Prepass: Wc[v] = fc2_w[v] @ glu_w[v]^T (fp32), emit bf16 hi/lo packed.
//          bc[v] = fc2_b[v] @ glu_w[v]^T + glu_b[v]
// ------------------------------------------------------------------
#define PREP_SA    0
#define PREP_SB    66560
#define PREP_F2B   83200
#define PREP_SMEM  83712

__global__ __launch_bounds__(256) void prep_wc(
    const float* __restrict__ fc2_w, const float* __restrict__ fc2_b,
    const float* __restrict__ glu_w, const float* __restrict__ glu_b)
{
    extern __shared__ char smraw[];
    float* sA   = (float*)(smraw + PREP_SA);
    float* sB   = (float*)(smraw + PREP_SB);
    float* sf2b = (float*)(smraw + PREP_F2B);

    const int tid = threadIdx.x;
    const int v   = blockIdx.x;

    for (int i = tid; i < 16384; i += 256) {
        int h = i >> 7, k = i & 127;
        sA[h * 130 + k] = fc2_w[(size_t)v * 16384 + i];
    }
    if (tid < 128) sf2b[tid] = fc2_b[v * NH + tid];
    __syncthreads();

    const int h  = tid & 127;
    const int g0 = (tid >> 7) * 16;

    for (int gt = 0; gt < 8; gt++) {
        for (int i = tid; i < 4096; i += 256) {
            int g = i >> 7, k = i & 127;
            sB[g * 130 + k] = glu_w[(size_t)v * 32768 + gt * 4096 + i];
        }
        __syncthreads();

        ull acc[16];
        #pragma unroll
        for (int j = 0; j < 16; j++) acc[j] = 0ull;

        #pragma unroll 4
        for (int k2 = 0; k2 < 64; k2++) {
            ull a = *(const ull*)(sA + h * 130 + 2 * k2);
            #pragma unroll
            for (int j = 0; j < 16; j++)
                ffma2(acc[j], a, *(const ull*)(sB + (g0 + j) * 130 + 2 * k2));
        }
        #pragma unroll
        for (int j = 0; j < 16; j++) {
            int g = gt * 32 + g0 + j;
            float val = upk_sum(acc[j]);
            __nv_bfloat16 hi = __float2bfloat16(val);
            __nv_bfloat16 lo = __float2bfloat16(val - __bfloat162float(hi));
            size_t bi = (size_t)v * (64 * 528) + (size_t)(h >> 1) * 528 + 2 * g + (h & 1);
            g_bhi[bi] = hi;
            g_blo[bi] = lo;
        }
        if (tid < 32) {
            float s = 0.f;
            for (int k = 0; k < 128; k++) s += sf2b[k] * sB[tid * 130 + k];
            g_bc[v * 256 + gt * 32 + tid] = s + glu_b[(size_t)v * 256 + gt * 32 + tid];
        }
        __syncthreads();
    }
}

// ------------------------------------------------------------------
// Kernel 1: weights branch -> softmax wts (unchanged, known-correct)
// ------------------------------------------------------------------
__global__ __launch_bounds__(256) void wts_kernel(
    const float* __restrict__ x,
    const float* __restrict__ wfc1_w, const float* __restrict__ wfc1_b,
    const float* __restrict__ wfc2_w, const float* __restrict__ wfc2_b,
    const float* __restrict__ wglu_w, const float* __restrict__ wglu_b,
    const float* __restrict__ wln_g,  const float* __restrict__ wln_b,
    float* __restrict__ wts_out)
{
    __shared__ float sx[8][NV];
    __shared__ float sa[8][NH];
    __shared__ float sb[8][NH];
    __shared__ float sg[8][2 * NV];

    const int tid = threadIdx.x;
    const int n0  = blockIdx.x * 8;

    for (int i = tid; i < 8 * NV; i += 256) sx[i / NV][i % NV] = x[n0 * NV + i];
    __syncthreads();

    const int h  = tid & 127;
    const int rh = tid >> 7;

    {
        float acc[4];
        float bia = wfc1_b[h];
        #pragma unroll
        for (int i = 0; i < 4; i++) acc[i] = bia;
        for (int v = 0; v < NV; v++) {
            float w = wfc1_w[v * NH + h];
            #pragma unroll
            for (int i = 0; i < 4; i++) acc[i] += sx[rh * 4 + i][v] * w;
        }
        #pragma unroll
        for (int i = 0; i < 4; i++) sa[rh * 4 + i][h] = elu1(acc[i]);
    }
    __syncthreads();

    {
        float acc[4];
        float bia = wfc2_b[h];
        #pragma unroll
        for (int i = 0; i < 4; i++) acc[i] = bia;
        for (int k = 0; k < NH; k++) {
            float w = wfc2_w[k * NH + h];
            #pragma unroll
            for (int i = 0; i < 4; i++) acc[i] += sa[rh * 4 + i][k] * w;
        }
        #pragma unroll
        for (int i = 0; i < 4; i++) sb[rh * 4 + i][h] = acc[i];
    }
    __syncthreads();

    for (int jb = 0; jb < 2 * NV; jb += 256) {
        int j = jb + tid;
        if (j < 2 * NV) {
            float acc[8];
            float bia = wglu_b[j];
            #pragma unroll
            for (int r = 0; r < 8; r++) acc[r] = bia;
            for (int k = 0; k < NH; k++) {
                float w = wglu_w[k * 2 * NV + j];
                #pragma unroll
                for (int r = 0; r < 8; r++) acc[r] += sb[r][k] * w;
            }
            #pragma unroll
            for (int r = 0; r < 8; r++) sg[r][j] = acc[r];
        }
    }
    __syncthreads();

    const int r = tid >> 5, l = tid & 31;
    float y[7];
    #pragma unroll
    for (int p = 0; p < 7; p++) {
        int v = l + 32 * p;
        if (v < NV) {
            float fo  = sg[r][v];
            float gt  = sg[r][v + NV];
            float sig = 1.f / (1.f + expf(-gt));
            y[p] = sx[r][v] + fo * sig;
        } else y[p] = 0.f;
    }
    float s = 0.f;
    #pragma unroll
    for (int p = 0; p < 7; p++) s += y[p];
    float mean = warp_sum(s) * (1.f / (float)NV);

    float s2 = 0.f;
    #pragma unroll
    for (int p = 0; p < 7; p++) {
        int v = l + 32 * p;
        if (v < NV) { float d = y[p] - mean; s2 += d * d; }
    }
    float rs = rsqrtf(warp_sum(s2) * (1.f / (float)NV) + 1e-5f);

    float z[7]; float zmax = -1e30f;
    #pragma unroll
    for (int p = 0; p < 7; p++) {
        int v = l + 32 * p;
        if (v < NV) {
            z[p] = (y[p] - mean) * rs * wln_g[v] + wln_b[v];
            zmax = fmaxf(zmax, z[p]);
        } else z[p] = -1e30f;
    }
    zmax = warp_max(zmax);
    float es = 0.f;
    #pragma unroll
    for (int p = 0; p < 7; p++) {
        int v = l + 32 * p;
        if (v < NV) { z[p] = expf(z[p] - zmax); es += z[p]; }
    }
    float inv = 1.f / warp_sum(es);
    #pragma unroll
    for (int p = 0; p < 7; p++) {
        int v = l + 32 * p;
        if (v < NV) {
            float wt = z[p] * inv;
            wts_out[(n0 + r) * NV + v] = wt;
            g_wtsT[v * NTOK + n0 + r]  = wt;
        }
    }
}

// ------------------------------------------------------------------
// Main kernel: HMMA (mma.sync bf16 3-term) per-variable GEMM + epilogue.
// CTA = (mg 0..7, v). 256 threads = 8 warps: 4 row-groups x {fc, gate}.
// smem bytes:
// ------------------------------------------------------------------
#define SB_BH   0                  // 64*264 u32 = 67584
#define SB_BL   67584
#define SB_AH   135168             // 64*68 u32  = 17408
#define SB_AL   152576
#define SB_GT   169984             // 64*132 f32 = 33792
#define SB_SX   203776
#define SB_SWT  204032
#define SB_F1W  204288
#define SB_F1B  204800
#define SB_SKW  205312
#define SB_SKB  205824
#define SB_LNG  206336
#define SB_LNB  206848
#define SB_BC   207360             // 256 f32
#define SB_SMEM 208384

__global__ __launch_bounds__(256, 1) void mma_main(
    const float* __restrict__ x,
    const float* __restrict__ fc1_w, const float* __restrict__ fc1_b,
    const float* __restrict__ skip_w, const float* __restrict__ skip_b,
    const float* __restrict__ ln_g,  const float* __restrict__ ln_b)
{
    extern __shared__ char smraw[];
    u32*   BH   = (u32*)(smraw + SB_BH);
    u32*   BL   = (u32*)(smraw + SB_BL);
    u32*   AH   = (u32*)(smraw + SB_AH);
    u32*   AL   = (u32*)(smraw + SB_AL);
    float* sgt  = (float*)(smraw + SB_GT);
    float* sx   = (float*)(smraw + SB_SX);
    float* swt  = (float*)(smraw + SB_SWT);
    float* sf1w = (float*)(smraw + SB_F1W);
    float* sf1b = (float*)(smraw + SB_F1B);
    float* sskw = (float*)(smraw + SB_SKW);
    float* sskb = (float*)(smraw + SB_SKB);
    float* slng = (float*)(smraw + SB_LNG);
    float* slnb = (float*)(smraw + SB_LNB);
    float* sbc  = (float*)(smraw + SB_BC);

    const int tid  = threadIdx.x;
    const int wid  = tid >> 5;
    const int lane = tid & 31;
    const int g    = lane >> 2;      // groupID
    const int tig  = lane & 3;       // thread-in-group
    const int half = wid >> 2;       // 0 = fc cols, 1 = gate cols
    const int w2   = wid & 3;
    const int r0   = 16 * w2;
    const int v    = blockIdx.y;

    // copy Wc hi/lo slabs (67584 B each)
    {
        const int4* srcH = (const int4*)(g_bhi + (size_t)v * (64 * 528));
        const int4* srcL = (const int4*)(g_blo + (size_t)v * (64 * 528));
        int4* dH = (int4*)BH;
        int4* dL = (int4*)BL;
        for (int i = tid; i < 4224; i += 256) { dH[i] = srcH[i]; dL[i] = srcL[i]; }
    }
    if (tid < 128) {
        sf1w[tid] = fc1_w[v * NH + tid];
        sf1b[tid] = fc1_b[v * NH + tid];
        sskw[tid] = skip_w[v * NH + tid];
        sskb[tid] = skip_b[v * NH + tid];
        slng[tid] = ln_g[tid];
        slnb[tid] = ln_b[tid];
    }
    sbc[tid] = g_bc[v * 256 + tid];

    for (int mi = 0; mi < 8; mi++) {
        const int n0 = (blockIdx.x * 8 + mi) * 64;
        __syncthreads();   // prev-unit consumers done; B copy done (mi=0)

        if (tid < 64) {
            sx[tid]  = x[(size_t)(n0 + tid) * NV + v];
            swt[tid] = g_wtsT[v * NTOK + n0 + tid];
        }
        // A staging: 64 rows x 64 k2 pairs, hi/lo
        for (int idx = tid; idx < 4096; idx += 256) {
            int row = idx >> 6, k2 = idx & 63;
            float xv = x[(size_t)(n0 + row) * NV + v];
            float t0 = elu1(xv * sf1w[2 * k2]     + sf1b[2 * k2]);
            float t1 = elu1(xv * sf1w[2 * k2 + 1] + sf1b[2 * k2 + 1]);
            u32 wh, wl;
            split2(t0, t1, wh, wl);
            AH[row * 68 + k2] = wh;
            AL[row * 68 + k2] = wl;
        }
        __syncthreads();

        float acc[16][4];
        #pragma unroll
        for (int s = 0; s < 16; s++)
            #pragma unroll
            for (int j = 0; j < 4; j++) acc[s][j] = 0.f;

        const int arow0 = (r0 + g) * 68;
        const int arow1 = (r0 + g + 8) * 68;

        for (int kk = 0; kk < 8; kk++) {
            const int k2a = 8 * kk + tig;
            u32 ah0 = AH[arow0 + k2a], ah1 = AH[arow1 + k2a];
            u32 ah2 = AH[arow0 + k2a + 4], ah3 = AH[arow1 + k2a + 4];
            u32 al0 = AL[arow0 + k2a], al1 = AL[arow1 + k2a];
            u32 al2 = AL[arow0 + k2a + 4], al3 = AL[arow1 + k2a + 4];
            const u32* bh = BH + k2a * 264 + half * 128 + g;
            const u32* bl = BL + k2a * 264 + half * 128 + g;
            #pragma unroll
            for (int s = 0; s < 16; s++) {
                u32 bh0 = bh[8 * s], bh1 = bh[1056 + 8 * s];
                u32 bl0 = bl[8 * s], bl1 = bl[1056 + 8 * s];
                mma16816(acc[s], ah0, ah1, ah2, ah3, bh0, bh1);
                mma16816(acc[s], ah0, ah1, ah2, ah3, bl0, bl1);
                mma16816(acc[s], al0, al1, al2, al3, bh0, bh1);
            }
        }

        // gate warps publish gate pre-activations (+bias) to smem
        if (half == 1) {
            #pragma unroll
            for (int s = 0; s < 16; s++)
                #pragma unroll
                for (int j = 0; j < 4; j++) {
                    int cg  = 8 * s + 2 * tig + (j & 1);
                    int row = r0 + g + 8 * (j >> 1);
                    sgt[row * 132 + cg] = acc[s][j] + sbc[128 + cg];
                }
        }
        __syncthreads();

        // fc warps: GLU + skip + row LayerNorm + weighted partial store
        if (half == 0) {
            float xr0 = sx[r0 + g],  xr1 = sx[r0 + g + 8];
            float s0 = 0.f, s1 = 0.f;
            #pragma unroll
            for (int s = 0; s < 16; s++)
                #pragma unroll
                for (int j = 0; j < 4; j++) {
                    int cg  = 8 * s + 2 * tig + (j & 1);
                    int row = r0 + g + 8 * (j >> 1);
                    float fv  = acc[s][j] + sbc[cg];
                    float gv  = sgt[row * 132 + cg];
                    float sig = 1.f / (1.f + __expf(-gv));
                    float xv  = (j & 2) ? xr1 : xr0;
                    float val = fv * sig + xv * sskw[cg] + sskb[cg];
                    acc[s][j] = val;
                    if (j & 2) s1 += val; else s0 += val;
                }
            s0 += __shfl_xor_sync(0xffffffffu, s0, 1);
            s0 += __shfl_xor_sync(0xffffffffu, s0, 2);
            s1 += __shfl_xor_sync(0xffffffffu, s1, 1);
            s1 += __shfl_xor_sync(0xffffffffu, s1, 2);
            float mean0 = s0 * (1.f / 128.f), mean1 = s1 * (1.f / 128.f);

            float d0 = 0.f, d1 = 0.f;
            #pragma unroll
            for (int s = 0; s < 16; s++)
                #pragma unroll
                for (int j = 0; j < 4; j++) {
                    float d = acc[s][j] - ((j & 2) ? mean1 : mean0);
                    if (j & 2) d1 += d * d; else d0 += d * d;
                }
            d0 += __shfl_xor_sync(0xffffffffu, d0, 1);
            d0 += __shfl_xor_sync(0xffffffffu, d0, 2);
            d1 += __shfl_xor_sync(0xffffffffu, d1, 1);
            d1 += __shfl_xor_sync(0xffffffffu, d1, 2);
            float rs0 = rsqrtf(d0 * (1.f / 128.f) + 1e-5f);
            float rs1 = rsqrtf(d1 * (1.f / 128.f) + 1e-5f);

            float wt0 = swt[r0 + g], wt1 = swt[r0 + g + 8];
            float* row0p = g_vpart + (size_t)v * ((size_t)NTOK * NH) + (size_t)(n0 + r0 + g) * NH;
            float* row1p = row0p + 8 * NH;
            #pragma unroll
            for (int s = 0; s < 16; s++)
                #pragma unroll
                for (int j = 0; j < 4; j++) {
                    int cg = 8 * s + 2 * tig + (j & 1);
                    float mean = (j & 2) ? mean1 : mean0;
                    float rs   = (j & 2) ? rs1 : rs0;
                    float wt   = (j & 2) ? wt1 : wt0;
                    float nm   = (acc[s][j] - mean) * rs * slng[cg] + slnb[cg];
                    ((j & 2) ? row1p : row0p)[cg] = wt * nm;
                }
        }
    }
}

// ------------------------------------------------------------------
// Reduce: sum 204 per-variable partials -> out
// ------------------------------------------------------------------
__global__ __launch_bounds__(256) void reduce_kernel(float* __restrict__ out)
{
    int i = blockIdx.x * 256 + threadIdx.x;
    const float* p = g_vpart + i;
    float s = 0.f;
    #pragma unroll 4
    for (int v = 0; v < NV; v++) s += p[(size_t)v * ((size_t)NTOK * NH)];
    out[i] = s;
}

// ------------------------------------------------------------------
extern "C" void kernel_launch(void* const* d_in, const int* in_sizes, int n_in,
                              void* d_out, int out_size) {
    const float* x      = (const float*)d_in[0];
    const float* fc1_w  = (const float*)d_in[1];
    const float* fc1_b  = (const float*)d_in[2];
    const float* fc2_w  = (const float*)d_in[3];
    const float* fc2_b  = (const float*)d_in[4];
    const float* glu_w  = (const float*)d_in[5];
    const float* glu_b  = (const float*)d_in[6];
    const float* skip_w = (const float*)d_in[7];
    const float* skip_b = (const float*)d_in[8];
    const float* ln_g   = (const float*)d_in[9];
    const float* ln_b   = (const float*)d_in[10];
    const float* wfc1_w = (const float*)d_in[11];
    const float* wfc1_b = (const float*)d_in[12];
    const float* wfc2_w = (const float*)d_in[13];
    const float* wfc2_b = (const float*)d_in[14];
    const float* wglu_w = (const float*)d_in[15];
    const float* wglu_b = (const float*)d_in[16];
    const float* wln_g  = (const float*)d_in[17];
    const float* wln_b  = (const float*)d_in[18];

    float* out = (float*)d_out;
    float* wts = out + (size_t)NTOK * NH;

    cudaFuncSetAttribute(prep_wc,  cudaFuncAttributeMaxDynamicSharedMemorySize, PREP_SMEM);
    cudaFuncSetAttribute(mma_main, cudaFuncAttributeMaxDynamicSharedMemorySize, SB_SMEM);

    prep_wc<<<NV, 256, PREP_SMEM>>>(fc2_w, fc2_b, glu_w, glu_b);
    wts_kernel<<<NTOK / 8, 256>>>(x, wfc1_w, wfc1_b, wfc2_w, wfc2_b,
                                  wglu_w, wglu_b, wln_g, wln_b, wts);
    mma_main<<<dim3(8, NV), 256, SB_SMEM>>>(
        x, fc1_w, fc1_b, skip_w, skip_b, ln_g, ln_b);
    reduce_kernel<<<(NTOK * NH) / 256, 256>>>(out);
}

// round 9
// speedup vs baseline: 2.1093x; 1.2877x over previous
#include <cuda_runtime.h>
#include <cuda_bf16.h>
#include <cstdint>

#define NTOK   4096
#define NV     204
#define NH     128
#define NH2    256

// ------------------------------------------------------------------
// Device scratch (zero-init, no allocations)
// ------------------------------------------------------------------
__device__ __nv_bfloat16 g_bhi[(size_t)NV * 64 * 528];
__device__ __nv_bfloat16 g_blo[(size_t)NV * 64 * 528];
__device__ float g_bc[NV * 256];
__device__ float g_vpart[(size_t)NV * NTOK * NH];
__device__ float g_wtsT[NV * NTOK];

typedef unsigned long long ull;
typedef uint32_t u32;

__device__ __forceinline__ void ffma2(ull &d, ull a, ull b) {
    asm("fma.rn.f32x2 %0, %1, %2, %0;" : "+l"(d) : "l"(a), "l"(b));
}
__device__ __forceinline__ float upk_sum(ull v) {
    float lo, hi;
    asm("mov.b64 {%0, %1}, %2;" : "=f"(lo), "=f"(hi) : "l"(v));
    return lo + hi;
}
__device__ __forceinline__ float warp_sum(float s) {
    #pragma unroll
    for (int o = 16; o > 0; o >>= 1) s += __shfl_xor_sync(0xffffffffu, s, o);
    return s;
}
__device__ __forceinline__ float warp_max(float s) {
    #pragma unroll
    for (int o = 16; o > 0; o >>= 1) s = fmaxf(s, __shfl_xor_sync(0xffffffffu, s, o));
    return s;
}
__device__ __forceinline__ float elu1(float t) { return t > 0.f ? t : expm1f(t); }
__device__ __forceinline__ float elu1f(float t) { return t > 0.f ? t : __expf(t) - 1.f; }

__device__ __forceinline__ void mma16816(float* d, u32 a0, u32 a1, u32 a2, u32 a3,
                                         u32 b0, u32 b1) {
    asm volatile("mma.sync.aligned.m16n8k16.row.col.f32.bf16.bf16.f32 "
        "{%0,%1,%2,%3}, {%4,%5,%6,%7}, {%8,%9}, {%0,%1,%2,%3};"
        : "+f"(d[0]), "+f"(d[1]), "+f"(d[2]), "+f"(d[3])
        : "r"(a0), "r"(a1), "r"(a2), "r"(a3), "r"(b0), "r"(b1));
}
__device__ __forceinline__ void split2(float t0, float t1, u32 &wh, u32 &wl) {
    __nv_bfloat16 h0 = __float2bfloat16(t0);
    __nv_bfloat16 l0 = __float2bfloat16(t0 - __bfloat162float(h0));
    __nv_bfloat16 h1 = __float2bfloat16(t1);
    __nv_bfloat16 l1 = __float2bfloat16(t1 - __bfloat162float(h1));
    wh = (u32)__bfloat16_as_ushort(h0) | ((u32)__bfloat16_as_ushort(h1) << 16);
    wl = (u32)__bfloat16_as_ushort(l0) | ((u32)__bfloat16_as_ushort(l1) << 16);
}

// ------------------------------------------------------------------
// Prepass: Wc[v] = fc2_w[v] @ glu_w[v]^T (fp32), emit bf16 hi/lo packed.
// ------------------------------------------------------------------
#define PREP_SA    0
#define PREP_SB    66560
#define PREP_F2B   83200
#define PREP_SMEM  83712

__global__ __launch_bounds__(256) void prep_wc(
    const float* __restrict__ fc2_w, const float* __restrict__ fc2_b,
    const float* __restrict__ glu_w, const float* __restrict__ glu_b)
{
    extern __shared__ char smraw[];
    float* sA   = (float*)(smraw + PREP_SA);
    float* sB   = (float*)(smraw + PREP_SB);
    float* sf2b = (float*)(smraw + PREP_F2B);

    const int tid = threadIdx.x;
    const int v   = blockIdx.x;

    for (int i = tid; i < 16384; i += 256) {
        int h = i >> 7, k = i & 127;
        sA[h * 130 + k] = fc2_w[(size_t)v * 16384 + i];
    }
    if (tid < 128) sf2b[tid] = fc2_b[v * NH + tid];
    __syncthreads();

    const int h  = tid & 127;
    const int g0 = (tid >> 7) * 16;

    for (int gt = 0; gt < 8; gt++) {
        for (int i = tid; i < 4096; i += 256) {
            int g = i >> 7, k = i & 127;
            sB[g * 130 + k] = glu_w[(size_t)v * 32768 + gt * 4096 + i];
        }
        __syncthreads();

        ull acc[16];
        #pragma unroll
        for (int j = 0; j < 16; j++) acc[j] = 0ull;

        #pragma unroll 4
        for (int k2 = 0; k2 < 64; k2++) {
            ull a = *(const ull*)(sA + h * 130 + 2 * k2);
            #pragma unroll
            for (int j = 0; j < 16; j++)
                ffma2(acc[j], a, *(const ull*)(sB + (g0 + j) * 130 + 2 * k2));
        }
        #pragma unroll
        for (int j = 0; j < 16; j++) {
            int g = gt * 32 + g0 + j;
            float val = upk_sum(acc[j]);
            __nv_bfloat16 hi = __float2bfloat16(val);
            __nv_bfloat16 lo = __float2bfloat16(val - __bfloat162float(hi));
            size_t bi = (size_t)v * (64 * 528) + (size_t)(h >> 1) * 528 + 2 * g + (h & 1);
            g_bhi[bi] = hi;
            g_blo[bi] = lo;
        }
        if (tid < 32) {
            float s = 0.f;
            for (int k = 0; k < 128; k++) s += sf2b[k] * sB[tid * 130 + k];
            g_bc[v * 256 + gt * 32 + tid] = s + glu_b[(size_t)v * 256 + gt * 32 + tid];
        }
        __syncthreads();
    }
}

// ------------------------------------------------------------------
// Kernel 1: weights branch -> softmax wts (unchanged, known-correct)
// ------------------------------------------------------------------
__global__ __launch_bounds__(256) void wts_kernel(
    const float* __restrict__ x,
    const float* __restrict__ wfc1_w, const float* __restrict__ wfc1_b,
    const float* __restrict__ wfc2_w, const float* __restrict__ wfc2_b,
    const float* __restrict__ wglu_w, const float* __restrict__ wglu_b,
    const float* __restrict__ wln_g,  const float* __restrict__ wln_b,
    float* __restrict__ wts_out)
{
    __shared__ float sx[8][NV];
    __shared__ float sa[8][NH];
    __shared__ float sb[8][NH];
    __shared__ float sg[8][2 * NV];

    const int tid = threadIdx.x;
    const int n0  = blockIdx.x * 8;

    for (int i = tid; i < 8 * NV; i += 256) sx[i / NV][i % NV] = x[n0 * NV + i];
    __syncthreads();

    const int h  = tid & 127;
    const int rh = tid >> 7;

    {
        float acc[4];
        float bia = wfc1_b[h];
        #pragma unroll
        for (int i = 0; i < 4; i++) acc[i] = bia;
        for (int v = 0; v < NV; v++) {
            float w = wfc1_w[v * NH + h];
            #pragma unroll
            for (int i = 0; i < 4; i++) acc[i] += sx[rh * 4 + i][v] * w;
        }
        #pragma unroll
        for (int i = 0; i < 4; i++) sa[rh * 4 + i][h] = elu1(acc[i]);
    }
    __syncthreads();

    {
        float acc[4];
        float bia = wfc2_b[h];
        #pragma unroll
        for (int i = 0; i < 4; i++) acc[i] = bia;
        for (int k = 0; k < NH; k++) {
            float w = wfc2_w[k * NH + h];
            #pragma unroll
            for (int i = 0; i < 4; i++) acc[i] += sa[rh * 4 + i][k] * w;
        }
        #pragma unroll
        for (int i = 0; i < 4; i++) sb[rh * 4 + i][h] = acc[i];
    }
    __syncthreads();

    for (int jb = 0; jb < 2 * NV; jb += 256) {
        int j = jb + tid;
        if (j < 2 * NV) {
            float acc[8];
            float bia = wglu_b[j];
            #pragma unroll
            for (int r = 0; r < 8; r++) acc[r] = bia;
            for (int k = 0; k < NH; k++) {
                float w = wglu_w[k * 2 * NV + j];
                #pragma unroll
                for (int r = 0; r < 8; r++) acc[r] += sb[r][k] * w;
            }
            #pragma unroll
            for (int r = 0; r < 8; r++) sg[r][j] = acc[r];
        }
    }
    __syncthreads();

    const int r = tid >> 5, l = tid & 31;
    float y[7];
    #pragma unroll
    for (int p = 0; p < 7; p++) {
        int v = l + 32 * p;
        if (v < NV) {
            float fo  = sg[r][v];
            float gt  = sg[r][v + NV];
            float sig = 1.f / (1.f + expf(-gt));
            y[p] = sx[r][v] + fo * sig;
        } else y[p] = 0.f;
    }
    float s = 0.f;
    #pragma unroll
    for (int p = 0; p < 7; p++) s += y[p];
    float mean = warp_sum(s) * (1.f / (float)NV);

    float s2 = 0.f;
    #pragma unroll
    for (int p = 0; p < 7; p++) {
        int v = l + 32 * p;
        if (v < NV) { float d = y[p] - mean; s2 += d * d; }
    }
    float rs = rsqrtf(warp_sum(s2) * (1.f / (float)NV) + 1e-5f);

    float z[7]; float zmax = -1e30f;
    #pragma unroll
    for (int p = 0; p < 7; p++) {
        int v = l + 32 * p;
        if (v < NV) {
            z[p] = (y[p] - mean) * rs * wln_g[v] + wln_b[v];
            zmax = fmaxf(zmax, z[p]);
        } else z[p] = -1e30f;
    }
    zmax = warp_max(zmax);
    float es = 0.f;
    #pragma unroll
    for (int p = 0; p < 7; p++) {
        int v = l + 32 * p;
        if (v < NV) { z[p] = expf(z[p] - zmax); es += z[p]; }
    }
    float inv = 1.f / warp_sum(es);
    #pragma unroll
    for (int p = 0; p < 7; p++) {
        int v = l + 32 * p;
        if (v < NV) {
            float wt = z[p] * inv;
            wts_out[(n0 + r) * NV + v] = wt;
            g_wtsT[v * NTOK + n0 + r]  = wt;
        }
    }
}

// ------------------------------------------------------------------
// Main kernel: HMMA bf16 3-term GEMM + all-warp coalesced epilogue.
// CTA = (mg 0..7, v). 8 warps: 4 row-groups x {fc, gate} for MMA,
// then all 8 warps row-parallel for the epilogue.
// Preact buffers (fc/gate, 64x132 f32 each) OVERLAY the A buffers,
// which are dead after the MMA phase.
// ------------------------------------------------------------------
#define SB_BH   0                  // 64*264 u32 = 67584
#define SB_BL   67584
#define SB_AH   135168             // A hi: 64*68 u32 = 17408
#define SB_AL   152576             // A lo
#define SB_FCB  135168             // fc preact 64*132 f32 = 33792 (overlays AH/AL)
#define SB_GTB  168960             // gate preact 64*132 f32 (ends 202752)
#define SB_SX   203776
#define SB_SWT  204032
#define SB_F1W  204288
#define SB_F1B  204800
#define SB_SKW  205312
#define SB_SKB  205824
#define SB_LNG  206336
#define SB_LNB  206848
#define SB_BC   207360             // 256 f32
#define SB_SMEM 208384

__global__ __launch_bounds__(256, 1) void mma_main(
    const float* __restrict__ x,
    const float* __restrict__ fc1_w, const float* __restrict__ fc1_b,
    const float* __restrict__ skip_w, const float* __restrict__ skip_b,
    const float* __restrict__ ln_g,  const float* __restrict__ ln_b)
{
    extern __shared__ char smraw[];
    u32*   BH   = (u32*)(smraw + SB_BH);
    u32*   BL   = (u32*)(smraw + SB_BL);
    u32*   AH   = (u32*)(smraw + SB_AH);
    u32*   AL   = (u32*)(smraw + SB_AL);
    float* fcb  = (float*)(smraw + SB_FCB);
    float* gtb  = (float*)(smraw + SB_GTB);
    float* sx   = (float*)(smraw + SB_SX);
    float* swt  = (float*)(smraw + SB_SWT);
    float* sf1w = (float*)(smraw + SB_F1W);
    float* sf1b = (float*)(smraw + SB_F1B);
    float* sskw = (float*)(smraw + SB_SKW);
    float* sskb = (float*)(smraw + SB_SKB);
    float* slng = (float*)(smraw + SB_LNG);
    float* slnb = (float*)(smraw + SB_LNB);
    float* sbc  = (float*)(smraw + SB_BC);

    const int tid  = threadIdx.x;
    const int wid  = tid >> 5;
    const int lane = tid & 31;
    const int g    = lane >> 2;      // groupID
    const int tig  = lane & 3;       // thread-in-group
    const int half = wid >> 2;       // 0 = fc cols, 1 = gate cols
    const int w2   = wid & 3;
    const int r0   = 16 * w2;
    const int v    = blockIdx.y;

    // copy Wc hi/lo slabs
    {
        const int4* srcH = (const int4*)(g_bhi + (size_t)v * (64 * 528));
        const int4* srcL = (const int4*)(g_blo + (size_t)v * (64 * 528));
        int4* dH = (int4*)BH;
        int4* dL = (int4*)BL;
        for (int i = tid; i < 4224; i += 256) { dH[i] = srcH[i]; dL[i] = srcL[i]; }
    }
    if (tid < 128) {
        sf1w[tid] = fc1_w[v * NH + tid];
        sf1b[tid] = fc1_b[v * NH + tid];
        sskw[tid] = skip_w[v * NH + tid];
        sskb[tid] = skip_b[v * NH + tid];
        slng[tid] = ln_g[tid];
        slnb[tid] = ln_b[tid];
    }
    sbc[tid] = g_bc[v * 256 + tid];

    for (int mi = 0; mi < 8; mi++) {
        const int n0 = (blockIdx.x * 8 + mi) * 64;
        __syncthreads();   // prev epilogue readers done; B copy done (mi=0)

        if (tid < 64) {
            sx[tid]  = x[(size_t)(n0 + tid) * NV + v];
            swt[tid] = g_wtsT[v * NTOK + n0 + tid];
        }
        // A staging: 64 rows x 64 k2 pairs, hi/lo
        for (int idx = tid; idx < 4096; idx += 256) {
            int row = idx >> 6, k2 = idx & 63;
            float xv = x[(size_t)(n0 + row) * NV + v];
            float t0 = elu1f(xv * sf1w[2 * k2]     + sf1b[2 * k2]);
            float t1 = elu1f(xv * sf1w[2 * k2 + 1] + sf1b[2 * k2 + 1]);
            u32 wh, wl;
            split2(t0, t1, wh, wl);
            AH[row * 68 + k2] = wh;
            AL[row * 68 + k2] = wl;
        }
        __syncthreads();

        float acc[16][4];
        #pragma unroll
        for (int s = 0; s < 16; s++)
            #pragma unroll
            for (int j = 0; j < 4; j++) acc[s][j] = 0.f;

        const int arow0 = (r0 + g) * 68;
        const int arow1 = (r0 + g + 8) * 68;

        for (int kk = 0; kk < 8; kk++) {
            const int k2a = 8 * kk + tig;
            u32 ah0 = AH[arow0 + k2a], ah1 = AH[arow1 + k2a];
            u32 ah2 = AH[arow0 + k2a + 4], ah3 = AH[arow1 + k2a + 4];
            u32 al0 = AL[arow0 + k2a], al1 = AL[arow1 + k2a];
            u32 al2 = AL[arow0 + k2a + 4], al3 = AL[arow1 + k2a + 4];
            const u32* bh = BH + k2a * 264 + half * 128 + g;
            const u32* bl = BL + k2a * 264 + half * 128 + g;
            // term-major: consecutive MMAs hit different accumulators
            #pragma unroll
            for (int s = 0; s < 16; s++) {
                u32 b0 = bh[8 * s], b1 = bh[1056 + 8 * s];
                mma16816(acc[s], ah0, ah1, ah2, ah3, b0, b1);
            }
            #pragma unroll
            for (int s = 0; s < 16; s++) {
                u32 b0 = bl[8 * s], b1 = bl[1056 + 8 * s];
                mma16816(acc[s], ah0, ah1, ah2, ah3, b0, b1);
            }
            #pragma unroll
            for (int s = 0; s < 16; s++) {
                u32 b0 = bh[8 * s], b1 = bh[1056 + 8 * s];
                mma16816(acc[s], al0, al1, al2, al3, b0, b1);
            }
        }
        __syncthreads();   // all MMA reads of AH/AL done before overlay write

        // publish biased preacts to smem (fc warps -> fcb, gate -> gtb)
        {
            float* pre = half ? gtb : fcb;
            const float* bias = sbc + half * 128;
            #pragma unroll
            for (int s = 0; s < 16; s++)
                #pragma unroll
                for (int j = 0; j < 4; j++) {
                    int cg  = 8 * s + 2 * tig + (j & 1);
                    int row = r0 + g + 8 * (j >> 1);
                    pre[row * 132 + cg] = acc[s][j] + bias[cg];
                }
        }
        __syncthreads();

        // all-warp epilogue: warp w handles rows 8w..8w+7
        {
            float lngv0 = slng[4 * lane],     lngv1 = slng[4 * lane + 1];
            float lngv2 = slng[4 * lane + 2], lngv3 = slng[4 * lane + 3];
            float lnbv0 = slnb[4 * lane],     lnbv1 = slnb[4 * lane + 1];
            float lnbv2 = slnb[4 * lane + 2], lnbv3 = slnb[4 * lane + 3];
            float skw0 = sskw[4 * lane],     skw1 = sskw[4 * lane + 1];
            float skw2 = sskw[4 * lane + 2], skw3 = sskw[4 * lane + 3];
            float skb0 = sskb[4 * lane],     skb1 = sskb[4 * lane + 1];
            float skb2 = sskb[4 * lane + 2], skb3 = sskb[4 * lane + 3];

            #pragma unroll
            for (int rr = 0; rr < 8; rr++) {
                int row = 8 * wid + rr;
                float4 f  = *(const float4*)(fcb + row * 132 + 4 * lane);
                float4 gt = *(const float4*)(gtb + row * 132 + 4 * lane);
                float xv  = sx[row];
                float wt  = swt[row];
                float val0 = f.x * (1.f / (1.f + __expf(-gt.x))) + xv * skw0 + skb0;
                float val1 = f.y * (1.f / (1.f + __expf(-gt.y))) + xv * skw1 + skb1;
                float val2 = f.z * (1.f / (1.f + __expf(-gt.z))) + xv * skw2 + skb2;
                float val3 = f.w * (1.f / (1.f + __expf(-gt.w))) + xv * skw3 + skb3;
                float mean = warp_sum(val0 + val1 + val2 + val3) * (1.f / 128.f);
                float d0 = val0 - mean, d1 = val1 - mean, d2 = val2 - mean, d3 = val3 - mean;
                float rs = rsqrtf(warp_sum(d0 * d0 + d1 * d1 + d2 * d2 + d3 * d3) * (1.f / 128.f) + 1e-5f);
                float4 o;
                o.x = wt * (d0 * rs * lngv0 + lnbv0);
                o.y = wt * (d1 * rs * lngv1 + lnbv1);
                o.z = wt * (d2 * rs * lngv2 + lnbv2);
                o.w = wt * (d3 * rs * lngv3 + lnbv3);
                *(float4*)(g_vpart + (size_t)v * ((size_t)NTOK * NH)
                           + (size_t)(n0 + row) * NH + 4 * lane) = o;
            }
        }
    }
}

// ------------------------------------------------------------------
// Reduce: sum 204 per-variable partials -> out
// ------------------------------------------------------------------
__global__ __launch_bounds__(256) void reduce_kernel(float* __restrict__ out)
{
    int i = blockIdx.x * 256 + threadIdx.x;
    const float* p = g_vpart + i;
    float s = 0.f;
    #pragma unroll 4
    for (int v = 0; v < NV; v++) s += p[(size_t)v * ((size_t)NTOK * NH)];
    out[i] = s;
}

// ------------------------------------------------------------------
extern "C" void kernel_launch(void* const* d_in, const int* in_sizes, int n_in,
                              void* d_out, int out_size) {
    const float* x      = (const float*)d_in[0];
    const float* fc1_w  = (const float*)d_in[1];
    const float* fc1_b  = (const float*)d_in[2];
    const float* fc2_w  = (const float*)d_in[3];
    const float* fc2_b  = (const float*)d_in[4];
    const float* glu_w  = (const float*)d_in[5];
    const float* glu_b  = (const float*)d_in[6];
    const float* skip_w = (const float*)d_in[7];
    const float* skip_b = (const float*)d_in[8];
    const float* ln_g   = (const float*)d_in[9];
    const float* ln_b   = (const float*)d_in[10];
    const float* wfc1_w = (const float*)d_in[11];
    const float* wfc1_b = (const float*)d_in[12];
    const float* wfc2_w = (const float*)d_in[13];
    const float* wfc2_b = (const float*)d_in[14];
    const float* wglu_w = (const float*)d_in[15];
    const float* wglu_b = (const float*)d_in[16];
    const float* wln_g  = (const float*)d_in[17];
    const float* wln_b  = (const float*)d_in[18];

    float* out = (float*)d_out;
    float* wts = out + (size_t)NTOK * NH;

    cudaFuncSetAttribute(prep_wc,  cudaFuncAttributeMaxDynamicSharedMemorySize, PREP_SMEM);
    cudaFuncSetAttribute(mma_main, cudaFuncAttributeMaxDynamicSharedMemorySize, SB_SMEM);

    prep_wc<<<NV, 256, PREP_SMEM>>>(fc2_w, fc2_b, glu_w, glu_b);
    wts_kernel<<<NTOK / 8, 256>>>(x, wfc1_w, wfc1_b, wfc2_w, wfc2_b,
                                  wglu_w, wglu_b, wln_g, wln_b, wts);
    mma_main<<<dim3(8, NV), 256, SB_SMEM>>>(
        x, fc1_w, fc1_b, skip_w, skip_b, ln_g, ln_b);
    reduce_kernel<<<(NTOK * NH) / 256, 256>>>(out);
}